// round 2
// baseline (speedup 1.0000x reference)
#include <cuda_runtime.h>
#include <math.h>

#define S_LEN 2048
#define BATCH 64
#define INSZ  512
#define HID   512
#define BH    (BATCH * HID)          // 32768
#define GATES 1024                   // compact z|n gates
#define M_TOT (S_LEN * BATCH)        // 131072

#define GCTA  128                    // persistent CTAs for recurrence
#define JPER  4                      // hidden units per CTA
#define HPAD  516                    // padded h row stride (floats), conflict-free

// 512 MB scratch for x-projection (z|n gates, bias folded in)
__device__ float g_xp[(size_t)M_TOT * GATES];
__device__ unsigned g_count;
__device__ unsigned g_sense;

__global__ void reset_kernel() {
    g_count = 0u;
    g_sense = 0u;
}

// ---------------------------------------------------------------------------
// Phase 1: C[m][n] = sum_k x[m][k] * Wih[HID + n][k] + bias[HID + n]
// Classic 128x128x8 tiled SGEMM, 256 threads, 8x8 per-thread micro-tile.
// ---------------------------------------------------------------------------
__global__ __launch_bounds__(256) void xproj_kernel(
    const float* __restrict__ A,     // x  [M_TOT, INSZ]
    const float* __restrict__ Wih,   // [3H, INSZ]
    const float* __restrict__ bias)  // [3H]
{
    __shared__ float As[8][128];
    __shared__ float Bs[8][128];

    const int bx  = blockIdx.x;      // n tile (8)
    const int by  = blockIdx.y;      // m tile (1024)
    const int tid = threadIdx.x;

    const int lrow = tid >> 1;           // 0..127
    const int lcol = (tid & 1) * 4;      // 0 or 4

    const float* Aptr = A   + (size_t)(by * 128 + lrow) * INSZ + lcol;
    const float* Wptr = Wih + (size_t)(HID + bx * 128 + lrow) * INSZ + lcol;

    const int ty = tid >> 4;   // 0..15 (m)
    const int tx = tid & 15;   // 0..15 (n)

    float acc[8][8];
#pragma unroll
    for (int i = 0; i < 8; i++)
#pragma unroll
        for (int j = 0; j < 8; j++) acc[i][j] = 0.f;

    for (int k0 = 0; k0 < INSZ; k0 += 8) {
        float4 av = *(const float4*)(Aptr + k0);
        float4 bv = *(const float4*)(Wptr + k0);
        As[lcol + 0][lrow] = av.x;
        As[lcol + 1][lrow] = av.y;
        As[lcol + 2][lrow] = av.z;
        As[lcol + 3][lrow] = av.w;
        Bs[lcol + 0][lrow] = bv.x;
        Bs[lcol + 1][lrow] = bv.y;
        Bs[lcol + 2][lrow] = bv.z;
        Bs[lcol + 3][lrow] = bv.w;
        __syncthreads();

#pragma unroll
        for (int k = 0; k < 8; k++) {
            float ar[8], br[8];
            *(float4*)(ar)     = *(const float4*)&As[k][ty * 8];
            *(float4*)(ar + 4) = *(const float4*)&As[k][ty * 8 + 4];
            *(float4*)(br)     = *(const float4*)&Bs[k][tx * 8];
            *(float4*)(br + 4) = *(const float4*)&Bs[k][tx * 8 + 4];
#pragma unroll
            for (int i = 0; i < 8; i++)
#pragma unroll
                for (int j = 0; j < 8; j++)
                    acc[i][j] = fmaf(ar[i], br[j], acc[i][j]);
        }
        __syncthreads();
    }

    const int n0 = bx * 128 + tx * 8;
    float bv[8];
#pragma unroll
    for (int j = 0; j < 8; j++) bv[j] = bias[HID + n0 + j];

    float* Cpt = g_xp + (size_t)(by * 128 + ty * 8) * GATES + n0;
#pragma unroll
    for (int i = 0; i < 8; i++) {
        float4 o0, o1;
        o0.x = acc[i][0] + bv[0]; o0.y = acc[i][1] + bv[1];
        o0.z = acc[i][2] + bv[2]; o0.w = acc[i][3] + bv[3];
        o1.x = acc[i][4] + bv[4]; o1.y = acc[i][5] + bv[5];
        o1.z = acc[i][6] + bv[6]; o1.w = acc[i][7] + bv[7];
        *(float4*)(Cpt + (size_t)i * GATES)     = o0;
        *(float4*)(Cpt + (size_t)i * GATES + 4) = o1;
    }
}

// ---------------------------------------------------------------------------
// Phase 2: persistent recurrence. 128 CTAs x 256 threads.
// CTA c owns hidden units j in [4c, 4c+4). Thread (b = tid&63, g = tid>>6)
// computes z_(b,j) and n_(b,j) then h_new directly. Grid barrier per step.
// h is broadcast through d_out[(t-1)*BH .. ] (fresh addresses every step).
// ---------------------------------------------------------------------------
extern __shared__ float smem[];

__global__ __launch_bounds__(256) void gru_kernel(
    const float* __restrict__ Whh,   // [3H, HID]
    float* __restrict__ out)         // [S*BH + BH]
{
    float* w_s = smem;               // [8][HID]  z rows then n rows
    float* h_s = smem + 8 * HID;     // [BATCH][HPAD]

    const int tid   = threadIdx.x;
    const int jbase = blockIdx.x * JPER;

    // Load the 8 weight rows this CTA needs (once for the whole sequence).
    for (int i = tid; i < 8 * HID; i += 256) {
        int s = i >> 9, k = i & 511;
        int row = (s < 4) ? (HID + jbase + s) : (2 * HID + jbase + s - 4);
        w_s[i] = Whh[(size_t)row * HID + k];
    }
    // h_0 = 0
    for (int i = tid; i < BATCH * HPAD; i += 256) h_s[i] = 0.f;
    __syncthreads();

    const int b = tid & 63;
    const int g = tid >> 6;          // 0..3
    const int j = jbase + g;
    const float* wz   = w_s + g * HID;
    const float* wn   = w_s + (g + 4) * HID;
    const float* hrow = h_s + b * HPAD;

    for (int t = 0; t < S_LEN; t++) {
        if (t > 0) {
            const float* hsrc = out + (size_t)(t - 1) * BH;
            for (int i = tid * 4; i < BH; i += 1024) {
                int bb = i >> 9, kk = i & 511;
                float4 v = *(const float4*)(hsrc + i);
                *(float4*)(h_s + bb * HPAD + kk) = v;
            }
        }
        __syncthreads();

        float accz = 0.f, accn = 0.f;
#pragma unroll 4
        for (int k = 0; k < HID; k += 4) {
            float4 h4 = *(const float4*)(hrow + k);
            float4 z4 = *(const float4*)(wz + k);
            float4 n4 = *(const float4*)(wn + k);
            accz = fmaf(h4.x, z4.x, accz);
            accz = fmaf(h4.y, z4.y, accz);
            accz = fmaf(h4.z, z4.z, accz);
            accz = fmaf(h4.w, z4.w, accz);
            accn = fmaf(h4.x, n4.x, accn);
            accn = fmaf(h4.y, n4.y, accn);
            accn = fmaf(h4.z, n4.z, accn);
            accn = fmaf(h4.w, n4.w, accn);
        }

        const float* xprow = g_xp + ((size_t)t * BATCH + b) * GATES;
        float gz = accz + xprow[j];
        float gn = accn + xprow[HID + j];
        float z  = 1.f / (1.f + expf(-gz));
        float n  = tanhf(gn);
        float hold = hrow[j];
        float hn = (1.f - z) * n + z * hold;

        out[(size_t)t * BH + b * HID + j] = hn;
        if (t == S_LEN - 1)
            out[(size_t)S_LEN * BH + b * HID + j] = hn;

        // ---- grid-wide barrier (monotonic count, reset per launch) ----
        __syncthreads();
        if (tid == 0) {
            __threadfence();
            unsigned target = (unsigned)(t + 1) * GCTA;
            unsigned old = atomicAdd(&g_count, 1u);
            if (old == target - 1u) {
                __threadfence();
                *((volatile unsigned*)&g_sense) = (unsigned)(t + 1);
            } else {
                while (*((volatile unsigned*)&g_sense) < (unsigned)(t + 1)) {}
            }
            __threadfence();
        }
        __syncthreads();
    }
}

extern "C" void kernel_launch(void* const* d_in, const int* in_sizes, int n_in,
                              void* d_out, int out_size) {
    const float* x    = (const float*)d_in[0];
    const float* wih  = (const float*)d_in[1];
    const float* whh  = (const float*)d_in[2];
    const float* bias = (const float*)d_in[3];
    float* out = (float*)d_out;

    static int configured = 0;
    if (!configured) {
        cudaFuncSetAttribute(gru_kernel,
                             cudaFuncAttributeMaxDynamicSharedMemorySize,
                             (8 * HID + BATCH * HPAD) * sizeof(float));
        configured = 1;
    }

    reset_kernel<<<1, 1>>>();

    dim3 grid1(GATES / 128, M_TOT / 128);
    xproj_kernel<<<grid1, 256>>>(x, wih, bias);

    size_t smem_bytes = (8 * HID + BATCH * HPAD) * sizeof(float);
    gru_kernel<<<GCTA, 256, smem_bytes>>>(whh, out);
}

// round 3
// speedup vs baseline: 1.0035x; 1.0035x over previous
#include <cuda_runtime.h>
#include <math.h>

#define S_LEN 2048
#define BATCH 64
#define INSZ  512
#define HID   512
#define BH    (BATCH * HID)          // 32768
#define GATES 1024                   // compact z|n gates
#define M_TOT (S_LEN * BATCH)        // 131072

#define GCTA  128                    // persistent CTAs for recurrence
#define JPER  4                      // hidden units per CTA
#define HPAD  516                    // padded h row stride (floats), conflict-free

// 512 MB scratch for x-projection (z|n gates, bias folded in)
__device__ float g_xp[(size_t)M_TOT * GATES];
__device__ unsigned g_count;
__device__ unsigned g_sense;

__global__ void reset_kernel() {
    g_count = 0u;
    g_sense = 0u;
}

// ---------------------------------------------------------------------------
// Phase 1: C[m][n] = sum_k x[m][k] * Wih[HID + n][k] + bias[HID + n]
// Classic 128x128x8 tiled SGEMM, 256 threads, 8x8 per-thread micro-tile.
// ---------------------------------------------------------------------------
__global__ __launch_bounds__(256) void xproj_kernel(
    const float* __restrict__ A,     // x  [M_TOT, INSZ]
    const float* __restrict__ Wih,   // [3H, INSZ]
    const float* __restrict__ bias)  // [3H]
{
    __shared__ float As[8][128];
    __shared__ float Bs[8][128];

    const int bx  = blockIdx.x;      // n tile (8)
    const int by  = blockIdx.y;      // m tile (1024)
    const int tid = threadIdx.x;

    const int lrow = tid >> 1;           // 0..127
    const int lcol = (tid & 1) * 4;      // 0 or 4

    const float* Aptr = A   + (size_t)(by * 128 + lrow) * INSZ + lcol;
    const float* Wptr = Wih + (size_t)(HID + bx * 128 + lrow) * INSZ + lcol;

    const int ty = tid >> 4;   // 0..15 (m)
    const int tx = tid & 15;   // 0..15 (n)

    float acc[8][8];
#pragma unroll
    for (int i = 0; i < 8; i++)
#pragma unroll
        for (int j = 0; j < 8; j++) acc[i][j] = 0.f;

    for (int k0 = 0; k0 < INSZ; k0 += 8) {
        float4 av = *(const float4*)(Aptr + k0);
        float4 bv = *(const float4*)(Wptr + k0);
        As[lcol + 0][lrow] = av.x;
        As[lcol + 1][lrow] = av.y;
        As[lcol + 2][lrow] = av.z;
        As[lcol + 3][lrow] = av.w;
        Bs[lcol + 0][lrow] = bv.x;
        Bs[lcol + 1][lrow] = bv.y;
        Bs[lcol + 2][lrow] = bv.z;
        Bs[lcol + 3][lrow] = bv.w;
        __syncthreads();

#pragma unroll
        for (int k = 0; k < 8; k++) {
            float ar[8], br[8];
            *(float4*)(ar)     = *(const float4*)&As[k][ty * 8];
            *(float4*)(ar + 4) = *(const float4*)&As[k][ty * 8 + 4];
            *(float4*)(br)     = *(const float4*)&Bs[k][tx * 8];
            *(float4*)(br + 4) = *(const float4*)&Bs[k][tx * 8 + 4];
#pragma unroll
            for (int i = 0; i < 8; i++)
#pragma unroll
                for (int j = 0; j < 8; j++)
                    acc[i][j] = fmaf(ar[i], br[j], acc[i][j]);
        }
        __syncthreads();
    }

    const int n0 = bx * 128 + tx * 8;
    float bv[8];
#pragma unroll
    for (int j = 0; j < 8; j++) bv[j] = bias[HID + n0 + j];

    float* Cpt = g_xp + (size_t)(by * 128 + ty * 8) * GATES + n0;
#pragma unroll
    for (int i = 0; i < 8; i++) {
        float4 o0, o1;
        o0.x = acc[i][0] + bv[0]; o0.y = acc[i][1] + bv[1];
        o0.z = acc[i][2] + bv[2]; o0.w = acc[i][3] + bv[3];
        o1.x = acc[i][4] + bv[4]; o1.y = acc[i][5] + bv[5];
        o1.z = acc[i][6] + bv[6]; o1.w = acc[i][7] + bv[7];
        *(float4*)(Cpt + (size_t)i * GATES)     = o0;
        *(float4*)(Cpt + (size_t)i * GATES + 4) = o1;
    }
}

// ---------------------------------------------------------------------------
// Phase 2: persistent recurrence. 128 CTAs x 256 threads.
// CTA c owns hidden units j in [4c, 4c+4). Thread (b = tid&63, g = tid>>6)
// computes z_(b,j) and n_(b,j) then h_new directly. Grid barrier per step.
// h is broadcast through d_out[(t-1)*BH .. ] (fresh addresses every step).
// ---------------------------------------------------------------------------
extern __shared__ float smem[];

__global__ __launch_bounds__(256) void gru_kernel(
    const float* __restrict__ Whh,   // [3H, HID]
    float* __restrict__ out)         // [S*BH + BH]
{
    float* w_s = smem;               // [8][HID]  z rows then n rows
    float* h_s = smem + 8 * HID;     // [BATCH][HPAD]

    const int tid   = threadIdx.x;
    const int jbase = blockIdx.x * JPER;

    // Load the 8 weight rows this CTA needs (once for the whole sequence).
    for (int i = tid; i < 8 * HID; i += 256) {
        int s = i >> 9, k = i & 511;
        int row = (s < 4) ? (HID + jbase + s) : (2 * HID + jbase + s - 4);
        w_s[i] = Whh[(size_t)row * HID + k];
    }
    // h_0 = 0
    for (int i = tid; i < BATCH * HPAD; i += 256) h_s[i] = 0.f;
    __syncthreads();

    const int b = tid & 63;
    const int g = tid >> 6;          // 0..3
    const int j = jbase + g;
    const float* wz   = w_s + g * HID;
    const float* wn   = w_s + (g + 4) * HID;
    const float* hrow = h_s + b * HPAD;

    for (int t = 0; t < S_LEN; t++) {
        if (t > 0) {
            const float* hsrc = out + (size_t)(t - 1) * BH;
            for (int i = tid * 4; i < BH; i += 1024) {
                int bb = i >> 9, kk = i & 511;
                float4 v = *(const float4*)(hsrc + i);
                *(float4*)(h_s + bb * HPAD + kk) = v;
            }
        }
        __syncthreads();

        float accz = 0.f, accn = 0.f;
#pragma unroll 4
        for (int k = 0; k < HID; k += 4) {
            float4 h4 = *(const float4*)(hrow + k);
            float4 z4 = *(const float4*)(wz + k);
            float4 n4 = *(const float4*)(wn + k);
            accz = fmaf(h4.x, z4.x, accz);
            accz = fmaf(h4.y, z4.y, accz);
            accz = fmaf(h4.z, z4.z, accz);
            accz = fmaf(h4.w, z4.w, accz);
            accn = fmaf(h4.x, n4.x, accn);
            accn = fmaf(h4.y, n4.y, accn);
            accn = fmaf(h4.z, n4.z, accn);
            accn = fmaf(h4.w, n4.w, accn);
        }

        const float* xprow = g_xp + ((size_t)t * BATCH + b) * GATES;
        float gz = accz + xprow[j];
        float gn = accn + xprow[HID + j];
        float z  = 1.f / (1.f + expf(-gz));
        float n  = tanhf(gn);
        float hold = hrow[j];
        float hn = (1.f - z) * n + z * hold;

        out[(size_t)t * BH + b * HID + j] = hn;
        if (t == S_LEN - 1)
            out[(size_t)S_LEN * BH + b * HID + j] = hn;

        // ---- grid-wide barrier (monotonic count, reset per launch) ----
        __syncthreads();
        if (tid == 0) {
            __threadfence();
            unsigned target = (unsigned)(t + 1) * GCTA;
            unsigned old = atomicAdd(&g_count, 1u);
            if (old == target - 1u) {
                __threadfence();
                *((volatile unsigned*)&g_sense) = (unsigned)(t + 1);
            } else {
                while (*((volatile unsigned*)&g_sense) < (unsigned)(t + 1)) {}
            }
            __threadfence();
        }
        __syncthreads();
    }
}

extern "C" void kernel_launch(void* const* d_in, const int* in_sizes, int n_in,
                              void* d_out, int out_size) {
    const float* x    = (const float*)d_in[0];
    const float* wih  = (const float*)d_in[1];
    const float* whh  = (const float*)d_in[2];
    const float* bias = (const float*)d_in[3];
    float* out = (float*)d_out;

    static int configured = 0;
    if (!configured) {
        cudaFuncSetAttribute(gru_kernel,
                             cudaFuncAttributeMaxDynamicSharedMemorySize,
                             (8 * HID + BATCH * HPAD) * sizeof(float));
        configured = 1;
    }

    reset_kernel<<<1, 1>>>();

    dim3 grid1(GATES / 128, M_TOT / 128);
    xproj_kernel<<<grid1, 256>>>(x, wih, bias);

    size_t smem_bytes = (8 * HID + BATCH * HPAD) * sizeof(float);
    gru_kernel<<<GCTA, 256, smem_bytes>>>(whh, out);
}

// round 4
// speedup vs baseline: 1.4470x; 1.4419x over previous
#include <cuda_runtime.h>
#include <math.h>

#define S_LEN 2048
#define BATCH 64
#define INSZ  512
#define HID   512
#define BH    (BATCH * HID)          // 32768
#define GATES 1024                   // compact z|n gates
#define M_TOT (S_LEN * BATCH)        // 131072

#define GCTA  128                    // persistent CTAs for recurrence
#define JPER  4                      // hidden units per CTA
#define HPAD  516                    // padded h row stride (floats): HPAD/4 odd -> conflict-free float4

// 512 MB scratch for x-projection (z|n gates, bias folded in)
__device__ float g_xp[(size_t)M_TOT * GATES];
__device__ unsigned g_count;
__device__ unsigned g_sense;

__global__ void reset_kernel() {
    g_count = 0u;
    g_sense = 0u;
}

// ---------------- packed fp32x2 helpers (B300 FFMA2 pipe) ----------------
__device__ __forceinline__ void fma2(unsigned long long& d,
                                     unsigned long long a,
                                     unsigned long long b) {
    asm("fma.rn.f32x2 %0, %1, %2, %0;" : "+l"(d) : "l"(a), "l"(b));
}
__device__ __forceinline__ unsigned long long dup2(float x) {
    unsigned long long r;
    asm("mov.b64 %0, {%1, %1};" : "=l"(r) : "f"(x));
    return r;
}
__device__ __forceinline__ float2 unpack2(unsigned long long v) {
    float2 f;
    asm("mov.b64 {%0, %1}, %2;" : "=f"(f.x), "=f"(f.y) : "l"(v));
    return f;
}

// ---------------------------------------------------------------------------
// Phase 1: C[m][n] = sum_k x[m][k] * Wih[HID + n][k] + bias[HID + n]
// 128x128x8 tiled SGEMM, 256 threads, 8x8 per-thread micro-tile, FFMA2.
// ---------------------------------------------------------------------------
__global__ __launch_bounds__(256, 2) void xproj_kernel(
    const float* __restrict__ A,     // x  [M_TOT, INSZ]
    const float* __restrict__ Wih,   // [3H, INSZ]
    const float* __restrict__ bias)  // [3H]
{
    __shared__ float As[8][128];
    __shared__ float Bs[8][128];

    const int bx  = blockIdx.x;      // n tile (8)
    const int by  = blockIdx.y;      // m tile (1024)
    const int tid = threadIdx.x;

    const int lrow = tid >> 1;           // 0..127
    const int lcol = (tid & 1) * 4;      // 0 or 4

    const float* Aptr = A   + (size_t)(by * 128 + lrow) * INSZ + lcol;
    const float* Wptr = Wih + (size_t)(HID + bx * 128 + lrow) * INSZ + lcol;

    const int ty = tid >> 4;   // 0..15 (m)
    const int tx = tid & 15;   // 0..15 (n)

    unsigned long long acc[8][4];
#pragma unroll
    for (int i = 0; i < 8; i++)
#pragma unroll
        for (int j = 0; j < 4; j++) acc[i][j] = 0ULL;

    for (int k0 = 0; k0 < INSZ; k0 += 8) {
        float4 av = *(const float4*)(Aptr + k0);
        float4 bv = *(const float4*)(Wptr + k0);
        As[lcol + 0][lrow] = av.x;
        As[lcol + 1][lrow] = av.y;
        As[lcol + 2][lrow] = av.z;
        As[lcol + 3][lrow] = av.w;
        Bs[lcol + 0][lrow] = bv.x;
        Bs[lcol + 1][lrow] = bv.y;
        Bs[lcol + 2][lrow] = bv.z;
        Bs[lcol + 3][lrow] = bv.w;
        __syncthreads();

#pragma unroll
        for (int k = 0; k < 8; k++) {
            float4 a0 = *(const float4*)&As[k][ty * 8];
            float4 a1 = *(const float4*)&As[k][ty * 8 + 4];
            ulonglong2 b0 = *(const ulonglong2*)&Bs[k][tx * 8];
            ulonglong2 b1 = *(const ulonglong2*)&Bs[k][tx * 8 + 4];
            float ar[8] = {a0.x, a0.y, a0.z, a0.w, a1.x, a1.y, a1.z, a1.w};
#pragma unroll
            for (int i = 0; i < 8; i++) {
                unsigned long long ad = dup2(ar[i]);
                fma2(acc[i][0], ad, b0.x);
                fma2(acc[i][1], ad, b0.y);
                fma2(acc[i][2], ad, b1.x);
                fma2(acc[i][3], ad, b1.y);
            }
        }
        __syncthreads();
    }

    const int n0 = bx * 128 + tx * 8;
    float bv[8];
#pragma unroll
    for (int j = 0; j < 8; j++) bv[j] = bias[HID + n0 + j];

    float* Cpt = g_xp + (size_t)(by * 128 + ty * 8) * GATES + n0;
#pragma unroll
    for (int i = 0; i < 8; i++) {
        float2 p0 = unpack2(acc[i][0]);
        float2 p1 = unpack2(acc[i][1]);
        float2 p2 = unpack2(acc[i][2]);
        float2 p3 = unpack2(acc[i][3]);
        float4 o0, o1;
        o0.x = p0.x + bv[0]; o0.y = p0.y + bv[1];
        o0.z = p1.x + bv[2]; o0.w = p1.y + bv[3];
        o1.x = p2.x + bv[4]; o1.y = p2.y + bv[5];
        o1.z = p3.x + bv[6]; o1.w = p3.y + bv[7];
        *(float4*)(Cpt + (size_t)i * GATES)     = o0;
        *(float4*)(Cpt + (size_t)i * GATES + 4) = o1;
    }
}

// ---------------------------------------------------------------------------
// Phase 2: persistent recurrence. 128 CTAs x 256 threads.
// CTA c owns hidden units j in [4c, 4c+4) (8 gate rows z|n in smem).
// Thread (b = tid&63, kq = tid>>6) computes the k-quarter [kq*128, kq*128+128)
// partial dot products for all 8 gate rows using packed FFMA2 over k-pairs,
// with 16 independent accumulator chains. Partials combined via smem tree;
// 64 threads (kq==0) apply the gate nonlinearities and store h_t coalesced.
// Grid barrier per step; h broadcast through d_out[(t-1)*BH ..].
// ---------------------------------------------------------------------------
extern __shared__ float smem[];

__global__ __launch_bounds__(256) void gru_kernel(
    const float* __restrict__ Whh,   // [3H, HID]
    float* __restrict__ out)         // [S*BH + BH]
{
    float* w_s   = smem;                         // [8][HID]  z rows then n rows
    float* h_s   = smem + 8 * HID;               // [BATCH][HPAD]
    float* red_s = h_s + BATCH * HPAD;           // [256][8]

    const int tid   = threadIdx.x;
    const int jbase = blockIdx.x * JPER;
    const int b     = tid & 63;
    const int kq    = tid >> 6;                  // 0..3 k-quarter

    // Load the 8 weight rows this CTA needs (once for the whole sequence).
    for (int i = tid; i < 8 * HID; i += 256) {
        int s = i >> 9, k = i & 511;
        int row = (s < 4) ? (HID + jbase + s) : (2 * HID + jbase + s - 4);
        w_s[i] = Whh[(size_t)row * HID + k];
    }
    // h_0 = 0
    for (int i = tid; i < BATCH * HPAD; i += 256) h_s[i] = 0.f;
    __syncthreads();

    const float* hrow  = h_s + b * HPAD + kq * 128;
    const float* wbase = w_s + kq * 128;
    float*       myred = red_s + tid * 8;

    for (int t = 0; t < S_LEN; t++) {
        if (t > 0) {
            const float* hsrc = out + (size_t)(t - 1) * BH;
            for (int i = tid * 4; i < BH; i += 1024) {
                int bb = i >> 9, kk = i & 511;
                float4 v = *(const float4*)(hsrc + i);
                *(float4*)(h_s + bb * HPAD + kk) = v;
            }
        }
        __syncthreads();

        // Prefetch xp for this step (independent of h; hidden under dot loop).
        float4 xpz, xpn;
        if (tid < 64) {
            const float* xprow = g_xp + ((size_t)t * BATCH + b) * GATES;
            xpz = *(const float4*)(xprow + jbase);
            xpn = *(const float4*)(xprow + HID + jbase);
        }

        unsigned long long acc_e[8], acc_o[8];
#pragma unroll
        for (int r = 0; r < 8; r++) { acc_e[r] = 0ULL; acc_o[r] = 0ULL; }

#pragma unroll 4
        for (int k = 0; k < 128; k += 4) {
            ulonglong2 h2 = *(const ulonglong2*)(hrow + k);
#pragma unroll
            for (int r = 0; r < 8; r++) {
                ulonglong2 w2 = *(const ulonglong2*)(wbase + r * HID + k);
                fma2(acc_e[r], h2.x, w2.x);
                fma2(acc_o[r], h2.y, w2.y);
            }
        }

        float s[8];
#pragma unroll
        for (int r = 0; r < 8; r++) {
            float2 e = unpack2(acc_e[r]);
            float2 o = unpack2(acc_o[r]);
            s[r] = (e.x + e.y) + (o.x + o.y);
        }
        float4 s0 = {s[0], s[1], s[2], s[3]};
        float4 s1 = {s[4], s[5], s[6], s[7]};
        *(float4*)(myred)     = s0;
        *(float4*)(myred + 4) = s1;
        __syncthreads();

        if (tid < 64) {
            float sum[8];
#pragma unroll
            for (int h = 0; h < 2; h++) {
                float4 p0 = *(const float4*)(red_s + (b      ) * 8 + h * 4);
                float4 p1 = *(const float4*)(red_s + (b +  64) * 8 + h * 4);
                float4 p2 = *(const float4*)(red_s + (b + 128) * 8 + h * 4);
                float4 p3 = *(const float4*)(red_s + (b + 192) * 8 + h * 4);
                sum[h * 4 + 0] = (p0.x + p1.x) + (p2.x + p3.x);
                sum[h * 4 + 1] = (p0.y + p1.y) + (p2.y + p3.y);
                sum[h * 4 + 2] = (p0.z + p1.z) + (p2.z + p3.z);
                sum[h * 4 + 3] = (p0.w + p1.w) + (p2.w + p3.w);
            }
            const float* xz = (const float*)&xpz;
            const float* xn = (const float*)&xpn;
            const float* hold = h_s + b * HPAD + jbase;
            float hv[4];
#pragma unroll
            for (int jj = 0; jj < 4; jj++) {
                float gz = sum[jj] + xz[jj];
                float gn = sum[4 + jj] + xn[jj];
                float z  = 1.f / (1.f + __expf(-gz));
                float e  = __expf(-2.f * fabsf(gn));          // in (0,1]; no overflow
                float tt = (1.f - e) / (1.f + e);
                float n  = copysignf(tt, gn);
                hv[jj] = (1.f - z) * n + z * hold[jj];
            }
            float4 hq = {hv[0], hv[1], hv[2], hv[3]};
            *(float4*)(out + (size_t)t * BH + b * HID + jbase) = hq;
            if (t == S_LEN - 1)
                *(float4*)(out + (size_t)S_LEN * BH + b * HID + jbase) = hq;
        }

        // ---- grid-wide barrier (monotonic count, reset per launch) ----
        __syncthreads();
        if (tid == 0) {
            __threadfence();
            unsigned target = (unsigned)(t + 1) * GCTA;
            unsigned old = atomicAdd(&g_count, 1u);
            if (old == target - 1u) {
                __threadfence();
                *((volatile unsigned*)&g_sense) = (unsigned)(t + 1);
            } else {
                while (*((volatile unsigned*)&g_sense) < (unsigned)(t + 1)) {}
            }
            __threadfence();
        }
        __syncthreads();
    }
}

extern "C" void kernel_launch(void* const* d_in, const int* in_sizes, int n_in,
                              void* d_out, int out_size) {
    const float* x    = (const float*)d_in[0];
    const float* wih  = (const float*)d_in[1];
    const float* whh  = (const float*)d_in[2];
    const float* bias = (const float*)d_in[3];
    float* out = (float*)d_out;

    static int configured = 0;
    if (!configured) {
        cudaFuncSetAttribute(gru_kernel,
                             cudaFuncAttributeMaxDynamicSharedMemorySize,
                             (8 * HID + BATCH * HPAD + 256 * 8) * sizeof(float));
        configured = 1;
    }

    reset_kernel<<<1, 1>>>();

    dim3 grid1(GATES / 128, M_TOT / 128);
    xproj_kernel<<<grid1, 256>>>(x, wih, bias);

    size_t smem_bytes = (8 * HID + BATCH * HPAD + 256 * 8) * sizeof(float);
    gru_kernel<<<GCTA, 256, smem_bytes>>>(whh, out);
}